// round 5
// baseline (speedup 1.0000x reference)
#include <cuda_runtime.h>
#include <cuda_bf16.h>
#include <math.h>
#include <stdint.h>

#define N 16384
#define D 1024
#define BM 256            // block tile rows
#define BN 128            // block tile cols
#define BK 64             // k-chunk in bf16 (=128 bytes per row)
#define NKT (D / BK)      // 16
#define NSTAGE 4

// ---------------- device globals ----------------
__device__ __align__(128) __nv_bfloat16 g_bf[(size_t)N * D];
__device__ unsigned g_rowmax[N];

__device__ __forceinline__ unsigned f2key(float f) {
    unsigned u = __float_as_uint(f);
    return (u & 0x80000000u) ? ~u : (u | 0x80000000u);
}
__device__ __forceinline__ float key2f(unsigned k) {
    unsigned u = (k & 0x80000000u) ? (k & 0x7FFFFFFFu) : ~k;
    return __uint_as_float(u);
}

__device__ __forceinline__ uint32_t smem_u32(const void* p) {
    uint32_t a;
    asm("{ .reg .u64 t; cvta.to.shared.u64 t, %1; cvt.u32.u64 %0, t; }" : "=r"(a) : "l"(p));
    return a;
}
#define SW128(off) ((off) ^ (((off) >> 3) & 0x70))

__device__ __forceinline__ void cp16(uint32_t dst, const void* src) {
    asm volatile("cp.async.cg.shared.global [%0], [%1], 16;" :: "r"(dst), "l"(src));
}

__device__ __forceinline__ void ldm_x4(uint32_t* r, uint32_t addr) {
    asm volatile("ldmatrix.sync.aligned.m8n8.x4.shared.b16 {%0,%1,%2,%3}, [%4];"
                 : "=r"(r[0]), "=r"(r[1]), "=r"(r[2]), "=r"(r[3]) : "r"(addr));
}

__device__ __forceinline__ void mma16816(float* c, const uint32_t* a, const uint32_t* b) {
    asm volatile(
        "mma.sync.aligned.m16n8k16.row.col.f32.bf16.bf16.f32 "
        "{%0,%1,%2,%3}, {%4,%5,%6,%7}, {%8,%9}, {%0,%1,%2,%3};"
        : "+f"(c[0]), "+f"(c[1]), "+f"(c[2]), "+f"(c[3])
        : "r"(a[0]), "r"(a[1]), "r"(a[2]), "r"(a[3]), "r"(b[0]), "r"(b[1]));
}

// ---------------- kernel 1: L2-normalize rows -> bf16 ----------------
__global__ void normalize_kernel(const float* __restrict__ in) {
    int row = blockIdx.x;
    float4 v = ((const float4*)(in + (size_t)row * D))[threadIdx.x];
    float s = v.x * v.x + v.y * v.y + v.z * v.z + v.w * v.w;
    __shared__ float red[8];
    #pragma unroll
    for (int o = 16; o > 0; o >>= 1) s += __shfl_xor_sync(0xffffffffu, s, o);
    if ((threadIdx.x & 31) == 0) red[threadIdx.x >> 5] = s;
    __syncthreads();
    if (threadIdx.x < 8) {
        float t = red[threadIdx.x];
        #pragma unroll
        for (int o = 4; o > 0; o >>= 1) t += __shfl_xor_sync(0xffu, t, o);
        if (threadIdx.x == 0) red[0] = t;
    }
    __syncthreads();
    float scale = 1.0f / fmaxf(sqrtf(red[0]), 1e-12f);
    __nv_bfloat162 p0 = __nv_bfloat162(__float2bfloat16(v.x * scale), __float2bfloat16(v.y * scale));
    __nv_bfloat162 p1 = __nv_bfloat162(__float2bfloat16(v.z * scale), __float2bfloat16(v.w * scale));
    size_t base = (size_t)row * D + threadIdx.x * 4;
    ((__nv_bfloat162*)(g_bf + base))[0] = p0;
    ((__nv_bfloat162*)(g_bf + base))[1] = p1;
}

__global__ void init_rowmax_kernel() {
    int i = blockIdx.x * blockDim.x + threadIdx.x;
    if (i < N) g_rowmax[i] = 0u;
}

// ---------------- kernel 2: 256x128 gram tile, mma.sync bf16 ----------------
// per stage: A 256x128B = 32KB, B 128x128B = 16KB -> 48KB; 4 stages = 192KB
#define A_BYTES 32768
#define STAGE_BYTES 49152
#define SMEM_TOTAL (NSTAGE * STAGE_BYTES)

__global__ void __launch_bounds__(256, 1) gram_kernel() {
    int tj = blockIdx.x;        // col tile (128 wide), 0..127
    int ti = blockIdx.y;        // row tile (256 tall), 0..63
    if (tj < 2 * ti) return;    // keep tiles intersecting upper triangle

    extern __shared__ char smem[];
    __shared__ unsigned s_rmax[BM], s_cmax[BN];

    const int rowBase = ti * BM;
    const int colBase = tj * BN;
    const int tid  = threadIdx.x;
    const int lane = tid & 31;
    const int wid  = tid >> 5;       // 0..7
    const int wm   = wid & 3;        // 4 m-warps: rows wm*64..+63
    const int wn   = wid >> 2;       // 2 n-warps: cols wn*64..+63
    const bool diagTile = (tj == 2 * ti) || (tj == 2 * ti + 1);

    s_rmax[tid] = 0u;
    if (tid < BN) s_cmax[tid] = 0u;

    uint32_t sb = smem_u32(smem);

    // ---- stage loader: A 32KB (8 iters) + B 16KB (4 iters) ----
    auto load_stage = [&](int kt, int s) {
        int k0 = kt * BK;
        uint32_t base = sb + s * STAGE_BYTES;
        #pragma unroll
        for (int it = 0; it < 8; it++) {
            int i = tid + it * 256;
            int r = i >> 3, seg = i & 7;
            uint32_t off = SW128(r * 128 + seg * 16);
            cp16(base + off, g_bf + (size_t)(rowBase + r) * D + k0 + seg * 8);
        }
        #pragma unroll
        for (int it = 0; it < 4; it++) {
            int i = tid + it * 256;
            int r = i >> 3, seg = i & 7;
            uint32_t off = SW128(r * 128 + seg * 16);
            cp16(base + A_BYTES + off, g_bf + (size_t)(colBase + r) * D + k0 + seg * 8);
        }
        asm volatile("cp.async.commit_group;" ::: "memory");
    };

    float acc[4][8][4];
    #pragma unroll
    for (int mf = 0; mf < 4; mf++)
        #pragma unroll
        for (int nf = 0; nf < 8; nf++)
            #pragma unroll
            for (int e = 0; e < 4; e++) acc[mf][nf][e] = 0.0f;

    const int aRowL = (lane & 7) + ((lane >> 3) & 1) * 8;
    const int aColS = (lane >> 4) * 16;
    const int bRowL = (lane & 7) + (lane >> 4) * 8;
    const int bColS = ((lane >> 3) & 1) * 16;

    load_stage(0, 0);
    load_stage(1, 1);
    load_stage(2, 2);

    for (int kt = 0; kt < NKT; kt++) {
        int s = kt & (NSTAGE - 1);
        asm volatile("cp.async.wait_group 2;" ::: "memory");
        __syncthreads();
        if (kt + 3 < NKT) load_stage(kt + 3, (kt + 3) & (NSTAGE - 1));

        uint32_t aBase = sb + s * STAGE_BYTES;
        uint32_t bBase = aBase + A_BYTES;

        #pragma unroll
        for (int ks = 0; ks < 4; ks++) {
            int kb = ks * 32;
            uint32_t a[4][4], b[4][4];
            #pragma unroll
            for (int mf = 0; mf < 4; mf++) {
                int r = wm * 64 + mf * 16 + aRowL;
                ldm_x4(a[mf], aBase + SW128(r * 128 + kb + aColS));
            }
            #pragma unroll
            for (int np = 0; np < 4; np++) {
                int r = wn * 64 + np * 16 + bRowL;
                ldm_x4(b[np], bBase + SW128(r * 128 + kb + bColS));
            }
            #pragma unroll
            for (int mf = 0; mf < 4; mf++)
                #pragma unroll
                for (int np = 0; np < 4; np++) {
                    mma16816(acc[mf][2 * np],     a[mf], &b[np][0]);
                    mma16816(acc[mf][2 * np + 1], a[mf], &b[np][2]);
                }
        }
    }

    // ---- diagonal mask ----
    const int g  = lane >> 2;
    const int cq = lane & 3;
    if (diagTile) {
        #pragma unroll
        for (int mf = 0; mf < 4; mf++)
            #pragma unroll
            for (int nf = 0; nf < 8; nf++)
                #pragma unroll
                for (int e = 0; e < 4; e++) {
                    int row = rowBase + wm * 64 + mf * 16 + g + (e >> 1) * 8;
                    int col = colBase + wn * 64 + nf * 8 + 2 * cq + (e & 1);
                    if (row == col) acc[mf][nf][e] = -3.0f;
                }
    }

    // ---- row maxes ----
    #pragma unroll
    for (int mf = 0; mf < 4; mf++)
        #pragma unroll
        for (int h = 0; h < 2; h++) {
            float m = -3.0f;
            #pragma unroll
            for (int nf = 0; nf < 8; nf++) {
                m = fmaxf(m, acc[mf][nf][2 * h]);
                m = fmaxf(m, acc[mf][nf][2 * h + 1]);
            }
            m = fmaxf(m, __shfl_xor_sync(0xffffffffu, m, 1));
            m = fmaxf(m, __shfl_xor_sync(0xffffffffu, m, 2));
            if (cq == 0) atomicMax(&s_rmax[wm * 64 + mf * 16 + h * 8 + g], f2key(m));
        }

    // ---- col maxes ----
    #pragma unroll
    for (int nf = 0; nf < 8; nf++)
        #pragma unroll
        for (int e = 0; e < 2; e++) {
            float m = -3.0f;
            #pragma unroll
            for (int mf = 0; mf < 4; mf++) {
                m = fmaxf(m, acc[mf][nf][e]);
                m = fmaxf(m, acc[mf][nf][2 + e]);
            }
            m = fmaxf(m, __shfl_xor_sync(0xffffffffu, m, 4));
            m = fmaxf(m, __shfl_xor_sync(0xffffffffu, m, 8));
            m = fmaxf(m, __shfl_xor_sync(0xffffffffu, m, 16));
            if (g == 0) atomicMax(&s_cmax[wn * 64 + nf * 8 + 2 * cq + e], f2key(m));
        }
    __syncthreads();

    atomicMax(&g_rowmax[rowBase + tid], s_rmax[tid]);
    if (tid < BN) atomicMax(&g_rowmax[colBase + tid], s_cmax[tid]);
}

// ---------------- kernel 3: loss ----------------
__global__ void loss_kernel(float* __restrict__ out) {
    int tid = threadIdx.x;
    float s = 0.0f;
    for (int i = tid; i < N; i += blockDim.x) {
        float md = key2f(g_rowmax[i]);
        float d2 = fmaxf(2.0f - 2.0f * md, 0.0f);
        s += logf(sqrtf(d2) + 1e-8f);
    }
    __shared__ float red[32];
    #pragma unroll
    for (int o = 16; o > 0; o >>= 1) s += __shfl_xor_sync(0xffffffffu, s, o);
    if ((tid & 31) == 0) red[tid >> 5] = s;
    __syncthreads();
    if (tid < 32) {
        float t = red[tid];
        #pragma unroll
        for (int o = 16; o > 0; o >>= 1) t += __shfl_xor_sync(0xffffffffu, t, o);
        if (tid == 0) out[0] = -t / (float)N;
    }
}

// ---------------- launch ----------------
extern "C" void kernel_launch(void* const* d_in, const int* in_sizes, int n_in,
                              void* d_out, int out_size) {
    const float* feats = (const float*)d_in[0];
    float* out = (float*)d_out;

    cudaFuncSetAttribute(gram_kernel, cudaFuncAttributeMaxDynamicSharedMemorySize, SMEM_TOTAL);

    normalize_kernel<<<N, 256>>>(feats);
    init_rowmax_kernel<<<(N + 1023) / 1024, 1024>>>();
    dim3 grid(N / BN, N / BM);          // (128, 64); tj<2ti exits immediately
    gram_kernel<<<grid, 256, SMEM_TOTAL>>>();
    loss_kernel<<<1, 1024>>>(out);
}

// round 8
// speedup vs baseline: 1.0234x; 1.0234x over previous
#include <cuda_runtime.h>
#include <cuda_bf16.h>
#include <math.h>
#include <stdint.h>

#define N 16384
#define D 1024
#define BM 256            // block tile rows
#define BN 128            // block tile cols
#define BK 64             // k-chunk in bf16 (=128 bytes per row)
#define NKT (D / BK)      // 16
#define NSTAGE 4
#define NTHR 512

// ---------------- device globals ----------------
__device__ __align__(128) __nv_bfloat16 g_bf[(size_t)N * D];
__device__ unsigned g_rowmax[N];

__device__ __forceinline__ unsigned f2key(float f) {
    unsigned u = __float_as_uint(f);
    return (u & 0x80000000u) ? ~u : (u | 0x80000000u);
}
__device__ __forceinline__ float key2f(unsigned k) {
    unsigned u = (k & 0x80000000u) ? (k & 0x7FFFFFFFu) : ~k;
    return __uint_as_float(u);
}

__device__ __forceinline__ uint32_t smem_u32(const void* p) {
    uint32_t a;
    asm("{ .reg .u64 t; cvta.to.shared.u64 t, %1; cvt.u32.u64 %0, t; }" : "=r"(a) : "l"(p));
    return a;
}
#define SW128(off) ((off) ^ (((off) >> 3) & 0x70))

__device__ __forceinline__ void cp16(uint32_t dst, const void* src) {
    asm volatile("cp.async.cg.shared.global [%0], [%1], 16;" :: "r"(dst), "l"(src));
}

__device__ __forceinline__ void ldm_x4(uint32_t* r, uint32_t addr) {
    asm volatile("ldmatrix.sync.aligned.m8n8.x4.shared.b16 {%0,%1,%2,%3}, [%4];"
                 : "=r"(r[0]), "=r"(r[1]), "=r"(r[2]), "=r"(r[3]) : "r"(addr));
}

__device__ __forceinline__ void mma16816(float* c, const uint32_t* a, const uint32_t* b) {
    asm volatile(
        "mma.sync.aligned.m16n8k16.row.col.f32.bf16.bf16.f32 "
        "{%0,%1,%2,%3}, {%4,%5,%6,%7}, {%8,%9}, {%0,%1,%2,%3};"
        : "+f"(c[0]), "+f"(c[1]), "+f"(c[2]), "+f"(c[3])
        : "r"(a[0]), "r"(a[1]), "r"(a[2]), "r"(a[3]), "r"(b[0]), "r"(b[1]));
}

// ---------------- kernel 1: L2-normalize rows -> bf16 (+ rowmax init) ----------------
__global__ void normalize_kernel(const float* __restrict__ in) {
    int row = blockIdx.x;
    if (threadIdx.x == 0) g_rowmax[row] = 0u;   // fold init into this kernel
    float4 v = ((const float4*)(in + (size_t)row * D))[threadIdx.x];
    float s = v.x * v.x + v.y * v.y + v.z * v.z + v.w * v.w;
    __shared__ float red[8];
    #pragma unroll
    for (int o = 16; o > 0; o >>= 1) s += __shfl_xor_sync(0xffffffffu, s, o);
    if ((threadIdx.x & 31) == 0) red[threadIdx.x >> 5] = s;
    __syncthreads();
    if (threadIdx.x < 8) {
        float t = red[threadIdx.x];
        #pragma unroll
        for (int o = 4; o > 0; o >>= 1) t += __shfl_xor_sync(0xffu, t, o);
        if (threadIdx.x == 0) red[0] = t;
    }
    __syncthreads();
    float scale = 1.0f / fmaxf(sqrtf(red[0]), 1e-12f);
    __nv_bfloat162 p0 = __nv_bfloat162(__float2bfloat16(v.x * scale), __float2bfloat16(v.y * scale));
    __nv_bfloat162 p1 = __nv_bfloat162(__float2bfloat16(v.z * scale), __float2bfloat16(v.w * scale));
    size_t base = (size_t)row * D + threadIdx.x * 4;
    ((__nv_bfloat162*)(g_bf + base))[0] = p0;
    ((__nv_bfloat162*)(g_bf + base))[1] = p1;
}

// ---------------- kernel 2: 256x128 gram tile, 512 thr, warp tile 64x32 ----------------
// stage: A 256x128B = 32KB + B 128x128B = 16KB = 48KB; 4 stages = 192KB
#define A_BYTES 32768
#define STAGE_BYTES 49152
#define SMEM_TOTAL (NSTAGE * STAGE_BYTES)

__global__ void __launch_bounds__(NTHR, 1) gram_kernel() {
    int tj = blockIdx.x;        // col tile (128 wide), 0..127
    int ti = blockIdx.y;        // row tile (256 tall), 0..63
    if (tj < 2 * ti) return;    // tiles intersecting upper triangle

    extern __shared__ char smem[];
    __shared__ unsigned s_rmax[BM], s_cmax[BN];

    const int rowBase = ti * BM;
    const int colBase = tj * BN;
    const int tid  = threadIdx.x;
    const int lane = tid & 31;
    const int wid  = tid >> 5;       // 0..15
    const int wm   = wid & 3;        // rows wm*64..+63
    const int wn   = wid >> 2;       // cols wn*32..+31
    const bool diagTile = (tj == 2 * ti) || (tj == 2 * ti + 1);

    if (tid < BM) s_rmax[tid] = 0u;
    if (tid < BN) s_cmax[tid] = 0u;

    uint32_t sb = smem_u32(smem);

    // ---- stage loader: A 32KB (4 iters) + B 16KB (2 iters), 512 threads ----
    auto load_stage = [&](int kt, int s) {
        int k0 = kt * BK;
        uint32_t base = sb + s * STAGE_BYTES;
        #pragma unroll
        for (int it = 0; it < 4; it++) {
            int i = tid + it * NTHR;
            int r = i >> 3, seg = i & 7;
            uint32_t off = SW128(r * 128 + seg * 16);
            cp16(base + off, g_bf + (size_t)(rowBase + r) * D + k0 + seg * 8);
        }
        #pragma unroll
        for (int it = 0; it < 2; it++) {
            int i = tid + it * NTHR;
            int r = i >> 3, seg = i & 7;
            uint32_t off = SW128(r * 128 + seg * 16);
            cp16(base + A_BYTES + off, g_bf + (size_t)(colBase + r) * D + k0 + seg * 8);
        }
        asm volatile("cp.async.commit_group;" ::: "memory");
    };

    float acc[4][4][4];              // [mf 16-row][nf 8-col][vec4]
    #pragma unroll
    for (int mf = 0; mf < 4; mf++)
        #pragma unroll
        for (int nf = 0; nf < 4; nf++)
            #pragma unroll
            for (int e = 0; e < 4; e++) acc[mf][nf][e] = 0.0f;

    const int aRowL = (lane & 7) + ((lane >> 3) & 1) * 8;
    const int aColS = (lane >> 4) * 16;
    const int bRowL = (lane & 7) + (lane >> 4) * 8;
    const int bColS = ((lane >> 3) & 1) * 16;

    load_stage(0, 0);
    load_stage(1, 1);
    load_stage(2, 2);

    for (int kt = 0; kt < NKT; kt++) {
        int s = kt & (NSTAGE - 1);
        asm volatile("cp.async.wait_group 2;" ::: "memory");
        __syncthreads();             // loads visible + prev compute done
        if (kt + 3 < NKT) load_stage(kt + 3, (kt + 3) & (NSTAGE - 1));

        uint32_t aBase = sb + s * STAGE_BYTES;
        uint32_t bBase = aBase + A_BYTES;

        #pragma unroll
        for (int ks = 0; ks < 4; ks++) {
            int kb = ks * 32;
            uint32_t a[4][4], b[2][4];
            #pragma unroll
            for (int mf = 0; mf < 4; mf++) {
                int r = wm * 64 + mf * 16 + aRowL;
                ldm_x4(a[mf], aBase + SW128(r * 128 + kb + aColS));
            }
            #pragma unroll
            for (int np = 0; np < 2; np++) {   // 32 cols = 2 x (16-row ldm)
                int r = wn * 32 + np * 16 + bRowL;
                ldm_x4(b[np], bBase + SW128(r * 128 + kb + bColS));
            }
            #pragma unroll
            for (int mf = 0; mf < 4; mf++)
                #pragma unroll
                for (int np = 0; np < 2; np++) {
                    mma16816(acc[mf][2 * np],     a[mf], &b[np][0]);
                    mma16816(acc[mf][2 * np + 1], a[mf], &b[np][2]);
                }
        }
    }

    // ---- diagonal mask ----
    const int g  = lane >> 2;
    const int cq = lane & 3;
    if (diagTile) {
        #pragma unroll
        for (int mf = 0; mf < 4; mf++)
            #pragma unroll
            for (int nf = 0; nf < 4; nf++)
                #pragma unroll
                for (int e = 0; e < 4; e++) {
                    int row = rowBase + wm * 64 + mf * 16 + g + (e >> 1) * 8;
                    int col = colBase + wn * 32 + nf * 8 + 2 * cq + (e & 1);
                    if (row == col) acc[mf][nf][e] = -3.0f;
                }
    }

    // ---- row maxes (reduce over cols; shuffle over cq) ----
    #pragma unroll
    for (int mf = 0; mf < 4; mf++)
        #pragma unroll
        for (int h = 0; h < 2; h++) {
            float m = -3.0f;
            #pragma unroll
            for (int nf = 0; nf < 4; nf++) {
                m = fmaxf(m, acc[mf][nf][2 * h]);
                m = fmaxf(m, acc[mf][nf][2 * h + 1]);
            }
            m = fmaxf(m, __shfl_xor_sync(0xffffffffu, m, 1));
            m = fmaxf(m, __shfl_xor_sync(0xffffffffu, m, 2));
            if (cq == 0) atomicMax(&s_rmax[wm * 64 + mf * 16 + h * 8 + g], f2key(m));
        }

    // ---- col maxes (reduce over rows; shuffle over g) ----
    #pragma unroll
    for (int nf = 0; nf < 4; nf++)
        #pragma unroll
        for (int e = 0; e < 2; e++) {
            float m = -3.0f;
            #pragma unroll
            for (int mf = 0; mf < 4; mf++) {
                m = fmaxf(m, acc[mf][nf][e]);
                m = fmaxf(m, acc[mf][nf][2 + e]);
            }
            m = fmaxf(m, __shfl_xor_sync(0xffffffffu, m, 4));
            m = fmaxf(m, __shfl_xor_sync(0xffffffffu, m, 8));
            m = fmaxf(m, __shfl_xor_sync(0xffffffffu, m, 16));
            if (g == 0) atomicMax(&s_cmax[wn * 32 + nf * 8 + 2 * cq + e], f2key(m));
        }
    __syncthreads();

    if (tid < BM) atomicMax(&g_rowmax[rowBase + tid], s_rmax[tid]);
    if (tid < BN) atomicMax(&g_rowmax[colBase + tid], s_cmax[tid]);
}

// ---------------- kernel 3: loss ----------------
__global__ void loss_kernel(float* __restrict__ out) {
    int tid = threadIdx.x;
    float s = 0.0f;
    for (int i = tid; i < N; i += blockDim.x) {
        float md = key2f(g_rowmax[i]);
        float d2 = fmaxf(2.0f - 2.0f * md, 0.0f);
        s += logf(sqrtf(d2) + 1e-8f);
    }
    __shared__ float red[32];
    #pragma unroll
    for (int o = 16; o > 0; o >>= 1) s += __shfl_xor_sync(0xffffffffu, s, o);
    if ((tid & 31) == 0) red[tid >> 5] = s;
    __syncthreads();
    if (tid < 32) {
        float t = red[tid];
        #pragma unroll
        for (int o = 16; o > 0; o >>= 1) t += __shfl_xor_sync(0xffffffffu, t, o);
        if (tid == 0) out[0] = -t / (float)N;
    }
}

// ---------------- launch ----------------
extern "C" void kernel_launch(void* const* d_in, const int* in_sizes, int n_in,
                              void* d_out, int out_size) {
    const float* feats = (const float*)d_in[0];
    float* out = (float*)d_out;

    cudaFuncSetAttribute(gram_kernel, cudaFuncAttributeMaxDynamicSharedMemorySize, SMEM_TOTAL);

    normalize_kernel<<<N, 256>>>(feats);
    dim3 grid(N / BN, N / BM);          // (128, 64)
    gram_kernel<<<grid, NTHR, SMEM_TOTAL>>>();
    loss_kernel<<<1, 1024>>>(out);
}

// round 10
// speedup vs baseline: 1.1074x; 1.0821x over previous
#include <cuda_runtime.h>
#include <cuda_bf16.h>
#include <math.h>
#include <stdint.h>

#define N 16384
#define D 1024
#define BT 128            // block tile (M and N)
#define BK 64             // k-chunk in bf16 (=128 bytes per row)
#define NKT (D / BK)      // 16
#define NSTAGE 3

// ---------------- device globals ----------------
__device__ __align__(128) __nv_bfloat16 g_bf[(size_t)N * D];
__device__ unsigned g_rowmax[N];

__device__ __forceinline__ unsigned f2key(float f) {
    unsigned u = __float_as_uint(f);
    return (u & 0x80000000u) ? ~u : (u | 0x80000000u);
}
__device__ __forceinline__ float key2f(unsigned k) {
    unsigned u = (k & 0x80000000u) ? (k & 0x7FFFFFFFu) : ~k;
    return __uint_as_float(u);
}

__device__ __forceinline__ uint32_t smem_u32(const void* p) {
    uint32_t a;
    asm("{ .reg .u64 t; cvta.to.shared.u64 t, %1; cvt.u32.u64 %0, t; }" : "=r"(a) : "l"(p));
    return a;
}
#define SW128(off) ((off) ^ (((off) >> 3) & 0x70))

__device__ __forceinline__ void cp16(uint32_t dst, const void* src) {
    asm volatile("cp.async.cg.shared.global [%0], [%1], 16;" :: "r"(dst), "l"(src));
}

__device__ __forceinline__ void ldm_x4(uint32_t* r, uint32_t addr) {
    asm volatile("ldmatrix.sync.aligned.m8n8.x4.shared.b16 {%0,%1,%2,%3}, [%4];"
                 : "=r"(r[0]), "=r"(r[1]), "=r"(r[2]), "=r"(r[3]) : "r"(addr));
}

__device__ __forceinline__ void mma16816(float* c, const uint32_t* a, const uint32_t* b) {
    asm volatile(
        "mma.sync.aligned.m16n8k16.row.col.f32.bf16.bf16.f32 "
        "{%0,%1,%2,%3}, {%4,%5,%6,%7}, {%8,%9}, {%0,%1,%2,%3};"
        : "+f"(c[0]), "+f"(c[1]), "+f"(c[2]), "+f"(c[3])
        : "r"(a[0]), "r"(a[1]), "r"(a[2]), "r"(a[3]), "r"(b[0]), "r"(b[1]));
}

// ---------------- kernel 1: L2-normalize rows -> bf16 (+ rowmax init) ----------------
__global__ void normalize_kernel(const float* __restrict__ in) {
    int row = blockIdx.x;
    if (threadIdx.x == 0) g_rowmax[row] = 0u;
    float4 v = ((const float4*)(in + (size_t)row * D))[threadIdx.x];
    float s = v.x * v.x + v.y * v.y + v.z * v.z + v.w * v.w;
    __shared__ float red[8];
    #pragma unroll
    for (int o = 16; o > 0; o >>= 1) s += __shfl_xor_sync(0xffffffffu, s, o);
    if ((threadIdx.x & 31) == 0) red[threadIdx.x >> 5] = s;
    __syncthreads();
    if (threadIdx.x < 8) {
        float t = red[threadIdx.x];
        #pragma unroll
        for (int o = 4; o > 0; o >>= 1) t += __shfl_xor_sync(0xffu, t, o);
        if (threadIdx.x == 0) red[0] = t;
    }
    __syncthreads();
    float scale = 1.0f / fmaxf(sqrtf(red[0]), 1e-12f);
    __nv_bfloat162 p0 = __nv_bfloat162(__float2bfloat16(v.x * scale), __float2bfloat16(v.y * scale));
    __nv_bfloat162 p1 = __nv_bfloat162(__float2bfloat16(v.z * scale), __float2bfloat16(v.w * scale));
    size_t base = (size_t)row * D + threadIdx.x * 4;
    ((__nv_bfloat162*)(g_bf + base))[0] = p0;
    ((__nv_bfloat162*)(g_bf + base))[1] = p1;
}

// ---------------- kernel 2: 128x128 gram tile, 3-stage, one barrier/chunk ----------------
// stage: A 128x128B = 16KB + B 16KB = 32KB; 3 stages = 96KB; 2 CTAs/SM
#define A_OFF 0
#define B_OFF 16384
#define STAGE_BYTES 32768
#define SMEM_TOTAL (NSTAGE * STAGE_BYTES)

__global__ void __launch_bounds__(256, 2) gram_kernel() {
    int tj = blockIdx.x;        // col tile
    int ti = blockIdx.y;        // row tile
    if (ti > tj) return;        // upper triangle only

    extern __shared__ char smem[];
    __shared__ unsigned s_rmax[BT], s_cmax[BT];

    const int rowBase = ti * BT;
    const int colBase = tj * BT;
    const int tid  = threadIdx.x;
    const int lane = tid & 31;
    const int wid  = tid >> 5;       // 0..7
    const int wm   = wid & 3;        // rows wm*32..+31
    const int wn   = wid >> 2;       // cols wn*64..+63

    if (tid < BT) { s_rmax[tid] = 0u; s_cmax[tid] = 0u; }

    uint32_t sb = smem_u32(smem);

    auto load_stage = [&](int kt, int s) {
        int k0 = kt * BK;
        uint32_t base = sb + s * STAGE_BYTES;
        #pragma unroll
        for (int it = 0; it < 4; it++) {
            int i = tid + it * 256;                        // 0..1023
            int r = i >> 3, seg = i & 7;
            uint32_t off = SW128(r * 128 + seg * 16);
            cp16(base + A_OFF + off, g_bf + (size_t)(rowBase + r) * D + k0 + seg * 8);
            cp16(base + B_OFF + off, g_bf + (size_t)(colBase + r) * D + k0 + seg * 8);
        }
        asm volatile("cp.async.commit_group;" ::: "memory");
    };

    float acc[2][8][4];
    #pragma unroll
    for (int mf = 0; mf < 2; mf++)
        #pragma unroll
        for (int nf = 0; nf < 8; nf++)
            #pragma unroll
            for (int e = 0; e < 4; e++) acc[mf][nf][e] = 0.0f;

    const int aRowL = (lane & 7) + ((lane >> 3) & 1) * 8;
    const int aColS = (lane >> 4) * 16;
    const int bRowL = (lane & 7) + (lane >> 4) * 8;
    const int bColS = ((lane >> 3) & 1) * 16;

    load_stage(0, 0);
    load_stage(1, 1);

    #pragma unroll 1
    for (int kt = 0; kt < NKT; kt++) {
        int s = kt % NSTAGE;
        if (kt == NKT - 1) asm volatile("cp.async.wait_group 0;" ::: "memory");
        else               asm volatile("cp.async.wait_group 1;" ::: "memory");
        __syncthreads();   // load kt visible; all warps past compute of kt-1
        if (kt + 2 < NKT) load_stage(kt + 2, (kt + 2) % NSTAGE);   // targets stage (kt-1)%3

        uint32_t aBase = sb + s * STAGE_BYTES + A_OFF;
        uint32_t bBase = sb + s * STAGE_BYTES + B_OFF;

        #pragma unroll
        for (int ks = 0; ks < 4; ks++) {
            int kb = ks * 32;
            uint32_t a[2][4], b[4][4];
            #pragma unroll
            for (int mf = 0; mf < 2; mf++) {
                int r = wm * 32 + mf * 16 + aRowL;
                ldm_x4(a[mf], aBase + SW128(r * 128 + kb + aColS));
            }
            #pragma unroll
            for (int np = 0; np < 4; np++) {
                int r = wn * 64 + np * 16 + bRowL;
                ldm_x4(b[np], bBase + SW128(r * 128 + kb + bColS));
            }
            #pragma unroll
            for (int mf = 0; mf < 2; mf++)
                #pragma unroll
                for (int np = 0; np < 4; np++) {
                    mma16816(acc[mf][2 * np],     a[mf], &b[np][0]);
                    mma16816(acc[mf][2 * np + 1], a[mf], &b[np][2]);
                }
        }
    }

    // ---- diagonal mask ----
    const int g  = lane >> 2;
    const int cq = lane & 3;
    if (ti == tj) {
        #pragma unroll
        for (int mf = 0; mf < 2; mf++)
            #pragma unroll
            for (int nf = 0; nf < 8; nf++)
                #pragma unroll
                for (int e = 0; e < 4; e++) {
                    int row = wm * 32 + mf * 16 + g + (e >> 1) * 8;
                    int col = wn * 64 + nf * 8 + 2 * cq + (e & 1);
                    if (row == col) acc[mf][nf][e] = -3.0f;
                }
    }

    // ---- row maxes ----
    #pragma unroll
    for (int mf = 0; mf < 2; mf++)
        #pragma unroll
        for (int h = 0; h < 2; h++) {
            float m = -3.0f;
            #pragma unroll
            for (int nf = 0; nf < 8; nf++) {
                m = fmaxf(m, acc[mf][nf][2 * h]);
                m = fmaxf(m, acc[mf][nf][2 * h + 1]);
            }
            m = fmaxf(m, __shfl_xor_sync(0xffffffffu, m, 1));
            m = fmaxf(m, __shfl_xor_sync(0xffffffffu, m, 2));
            if (cq == 0) atomicMax(&s_rmax[wm * 32 + mf * 16 + h * 8 + g], f2key(m));
        }

    // ---- col maxes ----
    #pragma unroll
    for (int nf = 0; nf < 8; nf++)
        #pragma unroll
        for (int e = 0; e < 2; e++) {
            float m = -3.0f;
            #pragma unroll
            for (int mf = 0; mf < 2; mf++) {
                m = fmaxf(m, acc[mf][nf][e]);
                m = fmaxf(m, acc[mf][nf][2 + e]);
            }
            m = fmaxf(m, __shfl_xor_sync(0xffffffffu, m, 4));
            m = fmaxf(m, __shfl_xor_sync(0xffffffffu, m, 8));
            m = fmaxf(m, __shfl_xor_sync(0xffffffffu, m, 16));
            if (g == 0) atomicMax(&s_cmax[wn * 64 + nf * 8 + 2 * cq + e], f2key(m));
        }
    __syncthreads();

    if (tid < BT) {
        atomicMax(&g_rowmax[rowBase + tid], s_rmax[tid]);
    } else {
        int c = tid - BT;
        if (ti != tj) atomicMax(&g_rowmax[colBase + c], s_cmax[c]);
    }
}

// ---------------- kernel 3: loss ----------------
__global__ void loss_kernel(float* __restrict__ out) {
    int tid = threadIdx.x;
    float s = 0.0f;
    for (int i = tid; i < N; i += blockDim.x) {
        float md = key2f(g_rowmax[i]);
        float d2 = fmaxf(2.0f - 2.0f * md, 0.0f);
        s += logf(sqrtf(d2) + 1e-8f);
    }
    __shared__ float red[32];
    #pragma unroll
    for (int o = 16; o > 0; o >>= 1) s += __shfl_xor_sync(0xffffffffu, s, o);
    if ((tid & 31) == 0) red[tid >> 5] = s;
    __syncthreads();
    if (tid < 32) {
        float t = red[tid];
        #pragma unroll
        for (int o = 16; o > 0; o >>= 1) t += __shfl_xor_sync(0xffffffffu, t, o);
        if (tid == 0) out[0] = -t / (float)N;
    }
}

// ---------------- launch ----------------
extern "C" void kernel_launch(void* const* d_in, const int* in_sizes, int n_in,
                              void* d_out, int out_size) {
    const float* feats = (const float*)d_in[0];
    float* out = (float*)d_out;

    cudaFuncSetAttribute(gram_kernel, cudaFuncAttributeMaxDynamicSharedMemorySize, SMEM_TOTAL);

    normalize_kernel<<<N, 256>>>(feats);
    dim3 grid(N / BT, N / BT);          // (128,128); ti>tj exits immediately
    gram_kernel<<<grid, 256, SMEM_TOTAL>>>();
    loss_kernel<<<1, 1024>>>(out);
}